// round 14
// baseline (speedup 1.0000x reference)
#include <cuda_runtime.h>
#include <cuda_fp16.h>
#include <math.h>
#include <stdint.h>

// Problem constants (shapes fixed by the dataset)
constexpr int F    = 128;      // feature dim (D = H = O = 128)
constexpr int NMAX = 100000;   // B*S = 4*25000
constexpr int EMAX = 600000;
constexpr int SCAN_TILE = 1024;               // 256 threads x 4 items
constexpr int SCAN_SHIFT = 10;
constexpr int NBMAX = (NMAX + SCAN_TILE - 1) / SCAN_TILE;   // 98

// ---------------- scratch (static device globals; no runtime alloc) --------
// Self-cleaning invariant: every kernel that dirties cross-call state restores
// it to zero by the end of the call (counts via atomicSub, bn sums / done
// flags reset by their final consumers). Module-load zero-init covers call 1.
__device__ __half g_hw[(long long)NMAX * F];  // GEMM output, fp16 (reused both layers)
__device__ __half g_h1[(long long)NMAX * F];  // layer-1 aggregated output, fp16 (pre-BN)
__device__ int   g_counts[NMAX];
__device__ int   g_rowptr[NMAX + 1];
__device__ int   g_partials[NBMAX + 2];
__device__ int   g_cols[EMAX];
__device__ float g_dis[NMAX];
__device__ float g_bnsum[F];
__device__ float g_bnsq[F];
__device__ float g_scale[F];
__device__ float g_shift[F];
__device__ unsigned g_done_scan;
__device__ unsigned g_done_bn;

// ---------------- streams/events (created pre-main, outside mem checkpoints) --
namespace {
struct StreamHolder {
    cudaStream_t s2 = nullptr;
    cudaEvent_t ev_fork = nullptr, ev_join = nullptr;
    bool ok = false;
    StreamHolder() {
        ok = (cudaStreamCreateWithFlags(&s2, cudaStreamNonBlocking) == cudaSuccess) &&
             (cudaEventCreateWithFlags(&ev_fork, cudaEventDisableTiming) == cudaSuccess) &&
             (cudaEventCreateWithFlags(&ev_join, cudaEventDisableTiming) == cudaSuccess);
    }
};
StreamHolder g_sh;
}

// ---------------- PTX helpers ------------------------------------------------
__device__ __forceinline__ uint32_t smem_u32(const void* p) {
    uint32_t a;
    asm("{ .reg .u64 t; cvta.to.shared.u64 t, %1; cvt.u32.u64 %0, t; }"
        : "=r"(a) : "l"(p));
    return a;
}
__device__ __forceinline__ void ldm_x4(uint32_t* r, uint32_t addr) {
    asm volatile("ldmatrix.sync.aligned.m8n8.x4.shared.b16 {%0,%1,%2,%3}, [%4];"
                 : "=r"(r[0]), "=r"(r[1]), "=r"(r[2]), "=r"(r[3]) : "r"(addr));
}
__device__ __forceinline__ void mma16816(float* c, const uint32_t* a,
                                         const uint32_t* b) {
    asm volatile(
        "mma.sync.aligned.m16n8k16.row.col.f32.f16.f16.f32 "
        "{%0,%1,%2,%3}, {%4,%5,%6,%7}, {%8,%9}, {%0,%1,%2,%3};"
        : "+f"(c[0]), "+f"(c[1]), "+f"(c[2]), "+f"(c[3])
        : "r"(a[0]), "r"(a[1]), "r"(a[2]), "r"(a[3]), "r"(b[0]), "r"(b[1]));
}

// count: 4 edges per thread via int4 (row half of edge_index)
__global__ void k_count(const int* __restrict__ ei, int E) {
    int e = (blockIdx.x * blockDim.x + threadIdx.x) * 4;
    if (e + 3 < E) {
        int4 r = *(const int4*)(ei + e);
        atomicAdd(&g_counts[r.x], 1);
        atomicAdd(&g_counts[r.y], 1);
        atomicAdd(&g_counts[r.z], 1);
        atomicAdd(&g_counts[r.w], 1);
    } else {
        for (; e < E; e++) atomicAdd(&g_counts[ei[e]], 1);
    }
}

// scan1: 1024-node tiles (4 items/thread, ~98 blocks), shuffle scan; the LAST
// block (ticket) scans the <=256 block partials, then resets the done flag.
__global__ void __launch_bounds__(256) k_scan1(int N) {
    __shared__ int wsum[8];
    __shared__ unsigned s_t;
    int t = threadIdx.x;
    int lane = t & 31;
    int warp = t >> 5;
    int base = blockIdx.x * SCAN_TILE + t * 4;
    int c[4];
    if (base + 3 < N) {
        int4 v4 = *(const int4*)(g_counts + base);
        c[0] = v4.x; c[1] = v4.y; c[2] = v4.z; c[3] = v4.w;
    } else {
#pragma unroll
        for (int j = 0; j < 4; j++)
            c[j] = (base + j < N) ? g_counts[base + j] : 0;
    }
    int s = c[0] + c[1] + c[2] + c[3];
    int incl = s;
#pragma unroll
    for (int off = 1; off < 32; off <<= 1) {
        int u = __shfl_up_sync(0xffffffffu, incl, off);
        if (lane >= off) incl += u;
    }
    if (lane == 31) wsum[warp] = incl;
    __syncthreads();
    if (warp == 0) {
        int v = (lane < 8) ? wsum[lane] : 0;
        int sc = v;
#pragma unroll
        for (int off = 1; off < 8; off <<= 1) {
            int u = __shfl_up_sync(0xffffffffu, sc, off);
            if (lane >= off) sc += u;
        }
        if (lane < 8) wsum[lane] = sc - v;
        if (lane == 7) g_partials[blockIdx.x] = sc;
    }
    __syncthreads();
    int run = wsum[warp] + incl - s;
#pragma unroll
    for (int j = 0; j < 4; j++) {
        int i = base + j;
        if (i < N) {
            g_rowptr[i] = run;
            g_dis[i] = rsqrtf((float)(c[j] + 1));
        }
        run += c[j];
    }
    __syncthreads();
    if (t == 0) {
        __threadfence();
        s_t = atomicAdd(&g_done_scan, 1u);
    }
    __syncthreads();
    if (s_t == gridDim.x - 1) {
        __threadfence();
        int NB = gridDim.x;
        int v = (t < NB) ? g_partials[t] : 0;
        int incl2 = v;
#pragma unroll
        for (int off = 1; off < 32; off <<= 1) {
            int u = __shfl_up_sync(0xffffffffu, incl2, off);
            if (lane >= off) incl2 += u;
        }
        __syncthreads();
        if (lane == 31) wsum[warp] = incl2;
        __syncthreads();
        if (warp == 0) {
            int wv = (lane < 8) ? wsum[lane] : 0;
            int sc = wv;
#pragma unroll
            for (int off = 1; off < 8; off <<= 1) {
                int u = __shfl_up_sync(0xffffffffu, sc, off);
                if (lane >= off) sc += u;
            }
            if (lane < 8) wsum[lane] = sc - wv;
        }
        __syncthreads();
        int excl = wsum[warp] + incl2 - v;
        if (t < NB) g_partials[t] = excl;
        if (t == NB - 1) {
            g_rowptr[N] = v;
            g_partials[NB] = excl;
        }
        if (t == 0) g_done_scan = 0;
    }
}

// scatter: counts hold degrees; decrement to get a unique slot (self-clean).
__global__ void k_scatter(const int* __restrict__ ei, int E) {
    int e = blockIdx.x * blockDim.x + threadIdx.x;
    if (e < E) {
        int r = ei[e];
        int c = ei[E + e];
        int o = atomicSub(&g_counts[r], 1);
        g_cols[g_rowptr[r] + g_partials[r >> SCAN_SHIFT] + o - 1] = c;
    }
}

// ---------------- HMMA GEMM: C[N,128](fp16) = op(A)[N,128] @ W[128,128] ------
// W converted to transposed fp16 SMEM image inline (no prep kernel).
constexpr int APITCH = 136;  // fp16 elements per row (padded)
constexpr int PL_A   = 0;
constexpr int PL_B   = 128 * APITCH;
constexpr int GSMEM = 2 * 128 * APITCH * 2;  // bytes = 69632

template <bool BN, bool AHALF>
__global__ void __launch_bounds__(256, 2)
k_tgemm(const void* __restrict__ Av,
        const float* __restrict__ W,   // [k][n] fp32 row-major
        __half* __restrict__ C, int N) {
    extern __shared__ __half sm[];
    uint32_t sb = smem_u32(sm);
    int tid = threadIdx.x;
    int lane = tid & 31;
    int wid = tid >> 5;
    int row0 = blockIdx.x * 128;

    // inline W -> Bt image: sm[PL_B + n*APITCH + k] = (half)W[k][n]
#pragma unroll
    for (int i = tid; i < 4096; i += 256) {   // 4096 float4 chunks
        int k  = i >> 5;
        int n4 = (i & 31) * 4;
        float4 w = *(const float4*)(W + k * 128 + n4);
        sm[PL_B + (n4 + 0) * APITCH + k] = __float2half_rn(w.x);
        sm[PL_B + (n4 + 1) * APITCH + k] = __float2half_rn(w.y);
        sm[PL_B + (n4 + 2) * APITCH + k] = __float2half_rn(w.z);
        sm[PL_B + (n4 + 3) * APITCH + k] = __float2half_rn(w.w);
    }

    if (AHALF) {
        const __half* A = (const __half*)Av;
#pragma unroll
        for (int i = tid; i < 2048; i += 256) {
            int r  = i >> 4;
            int c8 = i & 15;
            uint4 u = make_uint4(0, 0, 0, 0);
            int gr = row0 + r;
            if (gr < N) u = *(const uint4*)(A + (long long)gr * 128 + c8 * 8);
            if (BN) {
                uint32_t* uu = &u.x;
#pragma unroll
                for (int j = 0; j < 4; j++) {
                    float2 f = __half22float2(*(__half2*)&uu[j]);
                    int cb = c8 * 8 + j * 2;
                    f.x = fmaxf(fmaf(f.x, g_scale[cb], g_shift[cb]), 0.f);
                    f.y = fmaxf(fmaf(f.y, g_scale[cb + 1], g_shift[cb + 1]), 0.f);
                    *(__half2*)&uu[j] = __floats2half2_rn(f.x, f.y);
                }
            }
            *(uint4*)(sm + PL_A + r * APITCH + c8 * 8) = u;
        }
    } else {
        const float* A = (const float*)Av;
#pragma unroll
        for (int i = tid; i < 4096; i += 256) {
            int r  = i >> 5;
            int c4 = i & 31;
            float4 v = make_float4(0.f, 0.f, 0.f, 0.f);
            int gr = row0 + r;
            if (gr < N) v = *(const float4*)(A + (long long)gr * 128 + c4 * 4);
            __half2 h01 = __floats2half2_rn(v.x, v.y);
            __half2 h23 = __floats2half2_rn(v.z, v.w);
            uint2 hu = make_uint2(*(uint32_t*)&h01, *(uint32_t*)&h23);
            *(uint2*)(sm + PL_A + r * APITCH + c4 * 4) = hu;
        }
    }
    __syncthreads();

    int mb = (wid >> 2) * 64;
    int nb = (wid & 3) * 32;

    float acc[4][4][4];
#pragma unroll
    for (int i = 0; i < 4; i++)
#pragma unroll
        for (int j = 0; j < 4; j++)
#pragma unroll
            for (int q = 0; q < 4; q++) acc[i][j][q] = 0.f;

    int a_row_in = lane & 15;
    int a_koff   = (lane >> 4) << 3;
    int b_row_in = (lane & 7) + ((lane >> 4) << 3);
    int b_koff   = ((lane >> 3) & 1) << 3;

#pragma unroll
    for (int ks = 0; ks < 8; ks++) {
        int k0 = ks * 16;
        uint32_t av[4][4];
#pragma unroll
        for (int mi = 0; mi < 4; mi++) {
            uint32_t off = (uint32_t)((mb + mi * 16 + a_row_in) * APITCH +
                                      k0 + a_koff) * 2;
            ldm_x4(av[mi], sb + PL_A * 2 + off);
        }
        uint32_t bh[4][2];
#pragma unroll
        for (int p = 0; p < 2; p++) {
            uint32_t off = (uint32_t)((nb + p * 16 + b_row_in) * APITCH +
                                      k0 + b_koff) * 2;
            uint32_t t4[4];
            ldm_x4(t4, sb + PL_B * 2 + off);
            bh[p * 2 + 0][0] = t4[0]; bh[p * 2 + 0][1] = t4[1];
            bh[p * 2 + 1][0] = t4[2]; bh[p * 2 + 1][1] = t4[3];
        }
#pragma unroll
        for (int mi = 0; mi < 4; mi++)
#pragma unroll
            for (int ni = 0; ni < 4; ni++)
                mma16816(acc[mi][ni], av[mi], bh[ni]);
    }

    int rbase = row0 + mb + (lane >> 2);
    int cbase = nb + (lane & 3) * 2;
#pragma unroll
    for (int mi = 0; mi < 4; mi++) {
        int r0 = rbase + mi * 16;
        int r1 = r0 + 8;
#pragma unroll
        for (int ni = 0; ni < 4; ni++) {
            int cc = cbase + ni * 8;
            if (r0 < N)
                *(__half2*)(C + (long long)r0 * 128 + cc) =
                    __floats2half2_rn(acc[mi][ni][0], acc[mi][ni][1]);
            if (r1 < N)
                *(__half2*)(C + (long long)r1 * 128 + cc) =
                    __floats2half2_rn(acc[mi][ni][2], acc[mi][ni][3]);
        }
    }
}

// ---------------- aggregation (round-11 grid-stride, warp/node, uint2) -------
template <bool BN>
__global__ void __launch_bounds__(256)
k_agg(const __half* __restrict__ hw, const float* __restrict__ bias,
      void* __restrict__ outv, int N,
      const float* __restrict__ gamma, const float* __restrict__ beta,
      float invN) {
    int lane = threadIdx.x & 31;
    int warp = threadIdx.x >> 5;
    int gw0 = blockIdx.x * 8 + warp;
    int stride = gridDim.x * 8;
    float4 bias4 = *(const float4*)(bias + lane * 4);
    float sx = 0.f, sy = 0.f, sz = 0.f, sw = 0.f;
    float qx = 0.f, qy = 0.f, qz = 0.f, qw = 0.f;

    for (int node = gw0; node < N; node += stride) {
        float dn = g_dis[node];
        int e0 = g_rowptr[node] + g_partials[node >> SCAN_SHIFT];
        int i1 = node + 1;
        int e1 = g_rowptr[i1] + g_partials[i1 >> SCAN_SHIFT];
        float ax = 0.f, ay = 0.f, az = 0.f, aw = 0.f;
        int e = e0;
        for (; e + 4 <= e1; e += 4) {
            int c0 = g_cols[e], c1 = g_cols[e + 1];
            int c2 = g_cols[e + 2], c3 = g_cols[e + 3];
            float d0 = g_dis[c0], d1 = g_dis[c1], d2 = g_dis[c2], d3 = g_dis[c3];
            uint2 u0 = *(const uint2*)(hw + (long long)c0 * 128 + lane * 4);
            uint2 u1 = *(const uint2*)(hw + (long long)c1 * 128 + lane * 4);
            uint2 u2 = *(const uint2*)(hw + (long long)c2 * 128 + lane * 4);
            uint2 u3 = *(const uint2*)(hw + (long long)c3 * 128 + lane * 4);
            float2 p, q2;
            p = __half22float2(*(__half2*)&u0.x); q2 = __half22float2(*(__half2*)&u0.y);
            ax = fmaf(d0, p.x, ax); ay = fmaf(d0, p.y, ay);
            az = fmaf(d0, q2.x, az); aw = fmaf(d0, q2.y, aw);
            p = __half22float2(*(__half2*)&u1.x); q2 = __half22float2(*(__half2*)&u1.y);
            ax = fmaf(d1, p.x, ax); ay = fmaf(d1, p.y, ay);
            az = fmaf(d1, q2.x, az); aw = fmaf(d1, q2.y, aw);
            p = __half22float2(*(__half2*)&u2.x); q2 = __half22float2(*(__half2*)&u2.y);
            ax = fmaf(d2, p.x, ax); ay = fmaf(d2, p.y, ay);
            az = fmaf(d2, q2.x, az); aw = fmaf(d2, q2.y, aw);
            p = __half22float2(*(__half2*)&u3.x); q2 = __half22float2(*(__half2*)&u3.y);
            ax = fmaf(d3, p.x, ax); ay = fmaf(d3, p.y, ay);
            az = fmaf(d3, q2.x, az); aw = fmaf(d3, q2.y, aw);
        }
        for (; e < e1; e++) {
            int c = g_cols[e];
            float d = g_dis[c];
            uint2 u = *(const uint2*)(hw + (long long)c * 128 + lane * 4);
            float2 p = __half22float2(*(__half2*)&u.x);
            float2 q2 = __half22float2(*(__half2*)&u.y);
            ax = fmaf(d, p.x, ax); ay = fmaf(d, p.y, ay);
            az = fmaf(d, q2.x, az); aw = fmaf(d, q2.y, aw);
        }
        // self loop
        {
            uint2 u = *(const uint2*)(hw + (long long)node * 128 + lane * 4);
            float2 p = __half22float2(*(__half2*)&u.x);
            float2 q2 = __half22float2(*(__half2*)&u.y);
            ax = fmaf(dn, p.x, ax); ay = fmaf(dn, p.y, ay);
            az = fmaf(dn, q2.x, az); aw = fmaf(dn, q2.y, aw);
        }
        ax = fmaf(dn, ax, bias4.x); ay = fmaf(dn, ay, bias4.y);
        az = fmaf(dn, az, bias4.z); aw = fmaf(dn, aw, bias4.w);
        if (BN) {
            __half* out = (__half*)outv;
            uint2 o;
            *(__half2*)&o.x = __floats2half2_rn(ax, ay);
            *(__half2*)&o.y = __floats2half2_rn(az, aw);
            *(uint2*)(out + (long long)node * 128 + lane * 4) = o;
            sx += ax; sy += ay; sz += az; sw += aw;
            qx = fmaf(ax, ax, qx); qy = fmaf(ay, ay, qy);
            qz = fmaf(az, az, qz); qw = fmaf(aw, aw, qw);
        } else {
            float* out = (float*)outv;
            *(float4*)(out + (long long)node * 128 + lane * 4) =
                make_float4(ax, ay, az, aw);
        }
    }

    if (BN) {
        __shared__ float ssum[8 * 128];
        __shared__ float ssq[8 * 128];
        __shared__ unsigned s_ticket;
        int fb = warp * 128 + lane * 4;
        ssum[fb + 0] = sx; ssum[fb + 1] = sy; ssum[fb + 2] = sz; ssum[fb + 3] = sw;
        ssq[fb + 0]  = qx; ssq[fb + 1]  = qy; ssq[fb + 2]  = qz; ssq[fb + 3]  = qw;
        __syncthreads();
        int t = threadIdx.x;
        if (t < 128) {
            float a = 0.f, b = 0.f;
#pragma unroll
            for (int w = 0; w < 8; w++) { a += ssum[w * 128 + t]; b += ssq[w * 128 + t]; }
            atomicAdd(&g_bnsum[t], a);
            atomicAdd(&g_bnsq[t], b);
        }
        __syncthreads();
        if (t == 0) {
            __threadfence();
            s_ticket = atomicAdd(&g_done_bn, 1u);
        }
        __syncthreads();
        if (s_ticket == gridDim.x - 1) {
            __threadfence();
            if (t < 128) {
                float mean = g_bnsum[t] * invN;
                float var  = g_bnsq[t] * invN - mean * mean;
                float sc   = gamma[t] * rsqrtf(var + 1e-5f);
                g_scale[t] = sc;
                g_shift[t] = fmaf(-mean, sc, beta[t]);
                g_bnsum[t] = 0.f;
                g_bnsq[t]  = 0.f;
            }
            if (t == 0) g_done_bn = 0;
        }
    }
}

// ---------------- launch -----------------------------------------------------
extern "C" void kernel_launch(void* const* d_in, const int* in_sizes, int n_in,
                              void* d_out, int out_size) {
    const float* x      = (const float*)d_in[0];
    const int*   ei     = (const int*)d_in[1];
    const float* W1     = (const float*)d_in[2];
    const float* b1     = (const float*)d_in[3];
    const float* gamma1 = (const float*)d_in[4];
    const float* beta1  = (const float*)d_in[5];
    const float* W2     = (const float*)d_in[6];
    const float* b2     = (const float*)d_in[7];
    float* out = (float*)d_out;

    int N = in_sizes[0] / F;
    int E = in_sizes[1] / 2;
    if (N > NMAX) N = NMAX;
    if (E > EMAX) E = EMAX;

    __half* hw_ptr = nullptr;
    __half* h1_ptr = nullptr;
    cudaGetSymbolAddress((void**)&hw_ptr, g_hw);
    cudaGetSymbolAddress((void**)&h1_ptr, g_h1);

    cudaFuncSetAttribute((const void*)k_tgemm<false, false>,
                         cudaFuncAttributeMaxDynamicSharedMemorySize, GSMEM);
    cudaFuncSetAttribute((const void*)k_tgemm<true, true>,
                         cudaFuncAttributeMaxDynamicSharedMemorySize, GSMEM);

    int NB = (N + SCAN_TILE - 1) / SCAN_TILE;
    int gblocks = (N + 127) / 128;
    int ablocks = 1184;
    bool fork = g_sh.ok;

    // ---- stream 2: layer-1 GEMM (W converted inline; independent of CSR) ----
    if (fork) {
        cudaEventRecord(g_sh.ev_fork, 0);
        cudaStreamWaitEvent(g_sh.s2, g_sh.ev_fork, 0);
        k_tgemm<false, false><<<gblocks, 256, GSMEM, g_sh.s2>>>(x, W1,
                                                                hw_ptr, N);
        cudaEventRecord(g_sh.ev_join, g_sh.s2);
    } else {
        k_tgemm<false, false><<<gblocks, 256, GSMEM>>>(x, W1, hw_ptr, N);
    }

    // ---- main stream: CSR build + norm (state self-cleans) ----
    k_count<<<(E / 4 + 255) / 256, 256>>>(ei, E);
    k_scan1<<<NB, 256>>>(N);
    k_scatter<<<(E + 255) / 256, 256>>>(ei, E);

    if (fork) cudaStreamWaitEvent(0, g_sh.ev_join, 0);

    // layer 1 aggregate (+fused BN finalize), fp16 h1
    k_agg<true><<<ablocks, 256>>>(hw_ptr, b1, h1_ptr, N, gamma1, beta1,
                                  1.0f / (float)N);

    // layer 2: (BN+ReLU fused) GEMM -> aggregate -> out (fp32)
    k_tgemm<true, true><<<gblocks, 256, GSMEM>>>(h1_ptr, W2, hw_ptr, N);
    k_agg<false><<<ablocks, 256>>>(hw_ptr, b2, out, N, nullptr, nullptr, 0.f);
}

// round 15
// speedup vs baseline: 1.2858x; 1.2858x over previous
#include <cuda_runtime.h>
#include <cuda_fp16.h>
#include <math.h>
#include <stdint.h>

// Problem constants (shapes fixed by the dataset)
constexpr int F    = 128;      // feature dim (D = H = O = 128)
constexpr int NMAX = 100000;   // B*S = 4*25000
constexpr int EMAX = 600000;
constexpr int SCAN_TILE = 1024;               // 256 threads x 4 items
constexpr int SCAN_SHIFT = 10;
constexpr int NBMAX = (NMAX + SCAN_TILE - 1) / SCAN_TILE;   // 98

// ---------------- scratch (static device globals; no runtime alloc) --------
// Self-cleaning invariant: every kernel that dirties cross-call state restores
// it to zero by the end of the call (counts via atomicSub, bn sums / done
// flags reset by their final consumers). Module-load zero-init covers call 1.
__device__ __half g_hw[(long long)NMAX * F];  // GEMM output, fp16 (reused both layers)
__device__ __half g_h1[(long long)NMAX * F];  // layer-1 aggregated output, fp16 (pre-BN)
__device__ int   g_counts[NMAX];
__device__ int   g_rowptr[NMAX + 1];
__device__ int   g_partials[NBMAX + 2];
__device__ int   g_cols[EMAX];
__device__ float g_dis[NMAX];
__device__ float g_bnsum[F];
__device__ float g_bnsq[F];
__device__ float g_scale[F];
__device__ float g_shift[F];
__device__ unsigned g_done_scan;
__device__ unsigned g_done_bn;
// Bt = W^T images, dense [n][k] fp16: [0]=W1 [1]=W2
__device__ __half g_Bimg[2][128 * 128];

// ---------------- streams/events (created pre-main, outside mem checkpoints) --
namespace {
struct StreamHolder {
    cudaStream_t s2 = nullptr;
    cudaEvent_t ev_fork = nullptr, ev_join = nullptr;
    bool ok = false;
    StreamHolder() {
        ok = (cudaStreamCreateWithFlags(&s2, cudaStreamNonBlocking) == cudaSuccess) &&
             (cudaEventCreateWithFlags(&ev_fork, cudaEventDisableTiming) == cudaSuccess) &&
             (cudaEventCreateWithFlags(&ev_join, cudaEventDisableTiming) == cudaSuccess);
    }
};
StreamHolder g_sh;
}

// ---------------- PTX helpers ------------------------------------------------
__device__ __forceinline__ uint32_t smem_u32(const void* p) {
    uint32_t a;
    asm("{ .reg .u64 t; cvta.to.shared.u64 t, %1; cvt.u32.u64 %0, t; }"
        : "=r"(a) : "l"(p));
    return a;
}
__device__ __forceinline__ void ldm_x4(uint32_t* r, uint32_t addr) {
    asm volatile("ldmatrix.sync.aligned.m8n8.x4.shared.b16 {%0,%1,%2,%3}, [%4];"
                 : "=r"(r[0]), "=r"(r[1]), "=r"(r[2]), "=r"(r[3]) : "r"(addr));
}
__device__ __forceinline__ void mma16816(float* c, const uint32_t* a,
                                         const uint32_t* b) {
    asm volatile(
        "mma.sync.aligned.m16n8k16.row.col.f32.f16.f16.f32 "
        "{%0,%1,%2,%3}, {%4,%5,%6,%7}, {%8,%9}, {%0,%1,%2,%3};"
        : "+f"(c[0]), "+f"(c[1]), "+f"(c[2]), "+f"(c[3])
        : "r"(a[0]), "r"(a[1]), "r"(a[2]), "r"(a[3]), "r"(b[0]), "r"(b[1]));
}

// ---------------- W preprocessing (stream 2, once per call) -------------------
__global__ void __launch_bounds__(256) k_prepw(const float* __restrict__ W1,
                                               const float* __restrict__ W2) {
    int i = blockIdx.x * 256 + threadIdx.x;  // 2*16384 total
    int layer = i >> 14;
    int r = i & 16383;
    int n = r >> 7;   // Bt row (output col)
    int k = r & 127;  // K
    const float* W = layer ? W2 : W1;
    g_Bimg[layer][n * 128 + k] = __float2half_rn(W[k * 128 + n]);
}

// count: 4 edges per thread via int4 (row half of edge_index)
__global__ void k_count(const int* __restrict__ ei, int E) {
    int e = (blockIdx.x * blockDim.x + threadIdx.x) * 4;
    if (e + 3 < E) {
        int4 r = *(const int4*)(ei + e);
        atomicAdd(&g_counts[r.x], 1);
        atomicAdd(&g_counts[r.y], 1);
        atomicAdd(&g_counts[r.z], 1);
        atomicAdd(&g_counts[r.w], 1);
    } else {
        for (; e < E; e++) atomicAdd(&g_counts[ei[e]], 1);
    }
}

// scan1: 1024-node tiles (4 items/thread, ~98 blocks), shuffle scan; the LAST
// block (ticket) scans the <=256 block partials, then resets the done flag.
__global__ void __launch_bounds__(256) k_scan1(int N) {
    __shared__ int wsum[8];
    __shared__ unsigned s_t;
    int t = threadIdx.x;
    int lane = t & 31;
    int warp = t >> 5;
    int base = blockIdx.x * SCAN_TILE + t * 4;
    int c[4];
    if (base + 3 < N) {
        int4 v4 = *(const int4*)(g_counts + base);
        c[0] = v4.x; c[1] = v4.y; c[2] = v4.z; c[3] = v4.w;
    } else {
#pragma unroll
        for (int j = 0; j < 4; j++)
            c[j] = (base + j < N) ? g_counts[base + j] : 0;
    }
    int s = c[0] + c[1] + c[2] + c[3];
    int incl = s;
#pragma unroll
    for (int off = 1; off < 32; off <<= 1) {
        int u = __shfl_up_sync(0xffffffffu, incl, off);
        if (lane >= off) incl += u;
    }
    if (lane == 31) wsum[warp] = incl;
    __syncthreads();
    if (warp == 0) {
        int v = (lane < 8) ? wsum[lane] : 0;
        int sc = v;
#pragma unroll
        for (int off = 1; off < 8; off <<= 1) {
            int u = __shfl_up_sync(0xffffffffu, sc, off);
            if (lane >= off) sc += u;
        }
        if (lane < 8) wsum[lane] = sc - v;
        if (lane == 7) g_partials[blockIdx.x] = sc;
    }
    __syncthreads();
    int run = wsum[warp] + incl - s;
#pragma unroll
    for (int j = 0; j < 4; j++) {
        int i = base + j;
        if (i < N) {
            g_rowptr[i] = run;
            g_dis[i] = rsqrtf((float)(c[j] + 1));
        }
        run += c[j];
    }
    __syncthreads();
    if (t == 0) {
        __threadfence();
        s_t = atomicAdd(&g_done_scan, 1u);
    }
    __syncthreads();
    if (s_t == gridDim.x - 1) {
        __threadfence();
        int NB = gridDim.x;
        int v = (t < NB) ? g_partials[t] : 0;
        int incl2 = v;
#pragma unroll
        for (int off = 1; off < 32; off <<= 1) {
            int u = __shfl_up_sync(0xffffffffu, incl2, off);
            if (lane >= off) incl2 += u;
        }
        __syncthreads();
        if (lane == 31) wsum[warp] = incl2;
        __syncthreads();
        if (warp == 0) {
            int wv = (lane < 8) ? wsum[lane] : 0;
            int sc = wv;
#pragma unroll
            for (int off = 1; off < 8; off <<= 1) {
                int u = __shfl_up_sync(0xffffffffu, sc, off);
                if (lane >= off) sc += u;
            }
            if (lane < 8) wsum[lane] = sc - wv;
        }
        __syncthreads();
        int excl = wsum[warp] + incl2 - v;
        if (t < NB) g_partials[t] = excl;
        if (t == NB - 1) {
            g_rowptr[N] = v;
            g_partials[NB] = excl;
        }
        if (t == 0) g_done_scan = 0;
    }
}

// scatter: counts hold degrees; decrement to get a unique slot (self-clean).
__global__ void k_scatter(const int* __restrict__ ei, int E) {
    int e = blockIdx.x * blockDim.x + threadIdx.x;
    if (e < E) {
        int r = ei[e];
        int c = ei[E + e];
        int o = atomicSub(&g_counts[r], 1);
        g_cols[g_rowptr[r] + g_partials[r >> SCAN_SHIFT] + o - 1] = c;
    }
}

// ---------------- HMMA GEMM: C[N,128](fp16) = op(A)[N,128] @ W[128,128] ------
constexpr int APITCH = 136;  // fp16 elements per row (padded)
constexpr int PL_A   = 0;
constexpr int PL_B   = 128 * APITCH;
constexpr int GSMEM = 2 * 128 * APITCH * 2;  // bytes = 69632

template <bool BN, bool AHALF>
__global__ void __launch_bounds__(256, 2)
k_tgemm(const void* __restrict__ Av,
        const __half* __restrict__ B,
        __half* __restrict__ C, int N) {
    extern __shared__ __half sm[];
    uint32_t sb = smem_u32(sm);
    int tid = threadIdx.x;
    int lane = tid & 31;
    int wid = tid >> 5;
    int row0 = blockIdx.x * 128;

#pragma unroll
    for (int i = tid; i < 2048; i += 256) {
        int r = i >> 4;
        int c = i & 15;
        float4 vh = ((const float4*)B)[i];
        *(float4*)(sm + PL_B + r * APITCH + c * 8) = vh;
    }

    if (AHALF) {
        const __half* A = (const __half*)Av;
#pragma unroll
        for (int i = tid; i < 2048; i += 256) {
            int r  = i >> 4;
            int c8 = i & 15;
            uint4 u = make_uint4(0, 0, 0, 0);
            int gr = row0 + r;
            if (gr < N) u = *(const uint4*)(A + (long long)gr * 128 + c8 * 8);
            if (BN) {
                uint32_t* uu = &u.x;
#pragma unroll
                for (int j = 0; j < 4; j++) {
                    float2 f = __half22float2(*(__half2*)&uu[j]);
                    int cb = c8 * 8 + j * 2;
                    f.x = fmaxf(fmaf(f.x, g_scale[cb], g_shift[cb]), 0.f);
                    f.y = fmaxf(fmaf(f.y, g_scale[cb + 1], g_shift[cb + 1]), 0.f);
                    *(__half2*)&uu[j] = __floats2half2_rn(f.x, f.y);
                }
            }
            *(uint4*)(sm + PL_A + r * APITCH + c8 * 8) = u;
        }
    } else {
        const float* A = (const float*)Av;
#pragma unroll
        for (int i = tid; i < 4096; i += 256) {
            int r  = i >> 5;
            int c4 = i & 31;
            float4 v = make_float4(0.f, 0.f, 0.f, 0.f);
            int gr = row0 + r;
            if (gr < N) v = *(const float4*)(A + (long long)gr * 128 + c4 * 4);
            __half2 h01 = __floats2half2_rn(v.x, v.y);
            __half2 h23 = __floats2half2_rn(v.z, v.w);
            uint2 hu = make_uint2(*(uint32_t*)&h01, *(uint32_t*)&h23);
            *(uint2*)(sm + PL_A + r * APITCH + c4 * 4) = hu;
        }
    }
    __syncthreads();

    int mb = (wid >> 2) * 64;
    int nb = (wid & 3) * 32;

    float acc[4][4][4];
#pragma unroll
    for (int i = 0; i < 4; i++)
#pragma unroll
        for (int j = 0; j < 4; j++)
#pragma unroll
            for (int q = 0; q < 4; q++) acc[i][j][q] = 0.f;

    int a_row_in = lane & 15;
    int a_koff   = (lane >> 4) << 3;
    int b_row_in = (lane & 7) + ((lane >> 4) << 3);
    int b_koff   = ((lane >> 3) & 1) << 3;

#pragma unroll
    for (int ks = 0; ks < 8; ks++) {
        int k0 = ks * 16;
        uint32_t av[4][4];
#pragma unroll
        for (int mi = 0; mi < 4; mi++) {
            uint32_t off = (uint32_t)((mb + mi * 16 + a_row_in) * APITCH +
                                      k0 + a_koff) * 2;
            ldm_x4(av[mi], sb + PL_A * 2 + off);
        }
        uint32_t bh[4][2];
#pragma unroll
        for (int p = 0; p < 2; p++) {
            uint32_t off = (uint32_t)((nb + p * 16 + b_row_in) * APITCH +
                                      k0 + b_koff) * 2;
            uint32_t t4[4];
            ldm_x4(t4, sb + PL_B * 2 + off);
            bh[p * 2 + 0][0] = t4[0]; bh[p * 2 + 0][1] = t4[1];
            bh[p * 2 + 1][0] = t4[2]; bh[p * 2 + 1][1] = t4[3];
        }
#pragma unroll
        for (int mi = 0; mi < 4; mi++)
#pragma unroll
            for (int ni = 0; ni < 4; ni++)
                mma16816(acc[mi][ni], av[mi], bh[ni]);
    }

    int rbase = row0 + mb + (lane >> 2);
    int cbase = nb + (lane & 3) * 2;
#pragma unroll
    for (int mi = 0; mi < 4; mi++) {
        int r0 = rbase + mi * 16;
        int r1 = r0 + 8;
#pragma unroll
        for (int ni = 0; ni < 4; ni++) {
            int cc = cbase + ni * 8;
            if (r0 < N)
                *(__half2*)(C + (long long)r0 * 128 + cc) =
                    __floats2half2_rn(acc[mi][ni][0], acc[mi][ni][1]);
            if (r1 < N)
                *(__half2*)(C + (long long)r1 * 128 + cc) =
                    __floats2half2_rn(acc[mi][ni][2], acc[mi][ni][3]);
        }
    }
}

// ---------------- aggregation (grid-stride, warp/node, uint2 lanes) ----------
template <bool BN>
__global__ void __launch_bounds__(256)
k_agg(const __half* __restrict__ hw, const float* __restrict__ bias,
      void* __restrict__ outv, int N,
      const float* __restrict__ gamma, const float* __restrict__ beta,
      float invN) {
    int lane = threadIdx.x & 31;
    int warp = threadIdx.x >> 5;
    int gw0 = blockIdx.x * 8 + warp;
    int stride = gridDim.x * 8;
    float4 bias4 = *(const float4*)(bias + lane * 4);
    float sx = 0.f, sy = 0.f, sz = 0.f, sw = 0.f;
    float qx = 0.f, qy = 0.f, qz = 0.f, qw = 0.f;

    for (int node = gw0; node < N; node += stride) {
        float dn = g_dis[node];
        int e0 = g_rowptr[node] + g_partials[node >> SCAN_SHIFT];
        int i1 = node + 1;
        int e1 = g_rowptr[i1] + g_partials[i1 >> SCAN_SHIFT];
        float ax = 0.f, ay = 0.f, az = 0.f, aw = 0.f;
        int e = e0;
        for (; e + 4 <= e1; e += 4) {
            int c0 = g_cols[e], c1 = g_cols[e + 1];
            int c2 = g_cols[e + 2], c3 = g_cols[e + 3];
            float d0 = g_dis[c0], d1 = g_dis[c1], d2 = g_dis[c2], d3 = g_dis[c3];
            uint2 u0 = *(const uint2*)(hw + (long long)c0 * 128 + lane * 4);
            uint2 u1 = *(const uint2*)(hw + (long long)c1 * 128 + lane * 4);
            uint2 u2 = *(const uint2*)(hw + (long long)c2 * 128 + lane * 4);
            uint2 u3 = *(const uint2*)(hw + (long long)c3 * 128 + lane * 4);
            float2 p, q2;
            p = __half22float2(*(__half2*)&u0.x); q2 = __half22float2(*(__half2*)&u0.y);
            ax = fmaf(d0, p.x, ax); ay = fmaf(d0, p.y, ay);
            az = fmaf(d0, q2.x, az); aw = fmaf(d0, q2.y, aw);
            p = __half22float2(*(__half2*)&u1.x); q2 = __half22float2(*(__half2*)&u1.y);
            ax = fmaf(d1, p.x, ax); ay = fmaf(d1, p.y, ay);
            az = fmaf(d1, q2.x, az); aw = fmaf(d1, q2.y, aw);
            p = __half22float2(*(__half2*)&u2.x); q2 = __half22float2(*(__half2*)&u2.y);
            ax = fmaf(d2, p.x, ax); ay = fmaf(d2, p.y, ay);
            az = fmaf(d2, q2.x, az); aw = fmaf(d2, q2.y, aw);
            p = __half22float2(*(__half2*)&u3.x); q2 = __half22float2(*(__half2*)&u3.y);
            ax = fmaf(d3, p.x, ax); ay = fmaf(d3, p.y, ay);
            az = fmaf(d3, q2.x, az); aw = fmaf(d3, q2.y, aw);
        }
        for (; e < e1; e++) {
            int c = g_cols[e];
            float d = g_dis[c];
            uint2 u = *(const uint2*)(hw + (long long)c * 128 + lane * 4);
            float2 p = __half22float2(*(__half2*)&u.x);
            float2 q2 = __half22float2(*(__half2*)&u.y);
            ax = fmaf(d, p.x, ax); ay = fmaf(d, p.y, ay);
            az = fmaf(d, q2.x, az); aw = fmaf(d, q2.y, aw);
        }
        // self loop
        {
            uint2 u = *(const uint2*)(hw + (long long)node * 128 + lane * 4);
            float2 p = __half22float2(*(__half2*)&u.x);
            float2 q2 = __half22float2(*(__half2*)&u.y);
            ax = fmaf(dn, p.x, ax); ay = fmaf(dn, p.y, ay);
            az = fmaf(dn, q2.x, az); aw = fmaf(dn, q2.y, aw);
        }
        ax = fmaf(dn, ax, bias4.x); ay = fmaf(dn, ay, bias4.y);
        az = fmaf(dn, az, bias4.z); aw = fmaf(dn, aw, bias4.w);
        if (BN) {
            __half* out = (__half*)outv;
            uint2 o;
            *(__half2*)&o.x = __floats2half2_rn(ax, ay);
            *(__half2*)&o.y = __floats2half2_rn(az, aw);
            *(uint2*)(out + (long long)node * 128 + lane * 4) = o;
            sx += ax; sy += ay; sz += az; sw += aw;
            qx = fmaf(ax, ax, qx); qy = fmaf(ay, ay, qy);
            qz = fmaf(az, az, qz); qw = fmaf(aw, aw, qw);
        } else {
            float* out = (float*)outv;
            *(float4*)(out + (long long)node * 128 + lane * 4) =
                make_float4(ax, ay, az, aw);
        }
    }

    if (BN) {
        __shared__ float ssum[8 * 128];
        __shared__ float ssq[8 * 128];
        __shared__ unsigned s_ticket;
        int fb = warp * 128 + lane * 4;
        ssum[fb + 0] = sx; ssum[fb + 1] = sy; ssum[fb + 2] = sz; ssum[fb + 3] = sw;
        ssq[fb + 0]  = qx; ssq[fb + 1]  = qy; ssq[fb + 2]  = qz; ssq[fb + 3]  = qw;
        __syncthreads();
        int t = threadIdx.x;
        if (t < 128) {
            float a = 0.f, b = 0.f;
#pragma unroll
            for (int w = 0; w < 8; w++) { a += ssum[w * 128 + t]; b += ssq[w * 128 + t]; }
            atomicAdd(&g_bnsum[t], a);
            atomicAdd(&g_bnsq[t], b);
        }
        __syncthreads();
        if (t == 0) {
            __threadfence();
            s_ticket = atomicAdd(&g_done_bn, 1u);
        }
        __syncthreads();
        if (s_ticket == gridDim.x - 1) {
            __threadfence();
            if (t < 128) {
                float mean = g_bnsum[t] * invN;
                float var  = g_bnsq[t] * invN - mean * mean;
                float sc   = gamma[t] * rsqrtf(var + 1e-5f);
                g_scale[t] = sc;
                g_shift[t] = fmaf(-mean, sc, beta[t]);
                g_bnsum[t] = 0.f;
                g_bnsq[t]  = 0.f;
            }
            if (t == 0) g_done_bn = 0;
        }
    }
}

// ---------------- launch -----------------------------------------------------
extern "C" void kernel_launch(void* const* d_in, const int* in_sizes, int n_in,
                              void* d_out, int out_size) {
    const float* x      = (const float*)d_in[0];
    const int*   ei     = (const int*)d_in[1];
    const float* W1     = (const float*)d_in[2];
    const float* b1     = (const float*)d_in[3];
    const float* gamma1 = (const float*)d_in[4];
    const float* beta1  = (const float*)d_in[5];
    const float* W2     = (const float*)d_in[6];
    const float* b2     = (const float*)d_in[7];
    float* out = (float*)d_out;

    int N = in_sizes[0] / F;
    int E = in_sizes[1] / 2;
    if (N > NMAX) N = NMAX;
    if (E > EMAX) E = EMAX;

    __half* hw_ptr = nullptr;
    __half* h1_ptr = nullptr;
    __half* bimg = nullptr;
    cudaGetSymbolAddress((void**)&hw_ptr, g_hw);
    cudaGetSymbolAddress((void**)&h1_ptr, g_h1);
    cudaGetSymbolAddress((void**)&bimg, g_Bimg);

    cudaFuncSetAttribute((const void*)k_tgemm<false, false>,
                         cudaFuncAttributeMaxDynamicSharedMemorySize, GSMEM);
    cudaFuncSetAttribute((const void*)k_tgemm<true, true>,
                         cudaFuncAttributeMaxDynamicSharedMemorySize, GSMEM);

    int NB = (N + SCAN_TILE - 1) / SCAN_TILE;
    int gblocks = (N + 127) / 128;
    int ablocks = 1184;
    bool fork = g_sh.ok;

    // ---- stream 2: W prep + layer-1 GEMM (independent of CSR build) ----
    if (fork) {
        cudaEventRecord(g_sh.ev_fork, 0);
        cudaStreamWaitEvent(g_sh.s2, g_sh.ev_fork, 0);
        k_prepw<<<128, 256, 0, g_sh.s2>>>(W1, W2);
        k_tgemm<false, false><<<gblocks, 256, GSMEM, g_sh.s2>>>(x, bimg,
                                                                hw_ptr, N);
        cudaEventRecord(g_sh.ev_join, g_sh.s2);
    } else {
        k_prepw<<<128, 256>>>(W1, W2);
        k_tgemm<false, false><<<gblocks, 256, GSMEM>>>(x, bimg, hw_ptr, N);
    }

    // ---- main stream: CSR build + norm (state self-cleans) ----
    k_count<<<(E / 4 + 255) / 256, 256>>>(ei, E);
    k_scan1<<<NB, 256>>>(N);
    k_scatter<<<(E + 255) / 256, 256>>>(ei, E);

    if (fork) cudaStreamWaitEvent(0, g_sh.ev_join, 0);

    // layer 1 aggregate (+fused BN finalize), fp16 h1
    k_agg<true><<<ablocks, 256>>>(hw_ptr, b1, h1_ptr, N, gamma1, beta1,
                                  1.0f / (float)N);

    // layer 2: (BN+ReLU fused) GEMM -> aggregate -> out (fp32)
    k_tgemm<true, true><<<gblocks, 256, GSMEM>>>(h1_ptr, bimg + 16384,
                                                 hw_ptr, N);
    k_agg<false><<<ablocks, 256>>>(hw_ptr, b2, out, N, nullptr, nullptr, 0.f);
}